// round 8
// baseline (speedup 1.0000x reference)
#include <cuda_runtime.h>
#include <math.h>

#define B_   64
#define T_   256
#define D_   512
#define U_   512
#define G3   1536   // 3*U

typedef unsigned long long ull;

// ---------------- device scratch (static: no runtime allocation) ----------
__device__ float g_GX[2][T_][B_][G3];      // e@W + b_in, per direction
__device__ float g_P[3][2][B_][G3];        // triple-buffered gate accumulator (atomic)

// per-direction barrier state, padded to separate cache lines
struct __align__(128) BarState { unsigned int count; unsigned int gen; unsigned int pad[30]; };
__device__ BarState g_bar[2];

// ---------------- f32x2 packed helpers ------------------------------------
__device__ __forceinline__ void fma2(ull& d, ull a, ull b) {
    asm("fma.rn.f32x2 %0, %1, %2, %3;" : "=l"(d) : "l"(a), "l"(b), "l"(d));
}
__device__ __forceinline__ ull dup2(float v) {
    ull r; asm("mov.b64 %0, {%1, %1};" : "=l"(r) : "f"(v)); return r;
}
__device__ __forceinline__ float2 unpk(ull v) {
    float2 f; asm("mov.b64 {%0, %1}, %2;" : "=f"(f.x), "=f"(f.y) : "l"(v)); return f;
}
__device__ __forceinline__ void red_add(float* addr, float v) {
    asm volatile("red.global.add.f32 [%0], %1;" :: "l"(addr), "f"(v) : "memory");
}

// ---------------- software barrier over one direction's 64 blocks ---------
__device__ __forceinline__ void dir_sync(int dir, unsigned nb) {
    volatile unsigned* vgen = (volatile unsigned*)&g_bar[dir].gen;
    __syncthreads();
    if (threadIdx.x == 0) {
        unsigned gen = *vgen;
        __threadfence();                       // order gen-read & prior stores before arrive
        if (atomicAdd(&g_bar[dir].count, 1u) == nb - 1u) {
            g_bar[dir].count = 0u;
            __threadfence();
            atomicAdd(&g_bar[dir].gen, 1u);
        } else {
            while (*vgen == gen) { __nanosleep(64); }
        }
        __threadfence();                       // acquire
    }
    __syncthreads();
}

// ======================================================================
// Kernel 1: GX[dir][t][b][:] = emb[x[b][t]] @ W_dir + b_in
// (proven scalar version: 64-col tiles, BK=16)
// ======================================================================
__global__ __launch_bounds__(256)
void k_input_gemm(const int* __restrict__ x,
                  const float* __restrict__ emb,
                  const float* __restrict__ Wf,
                  const float* __restrict__ bf,
                  const float* __restrict__ Wb,
                  const float* __restrict__ bb)
{
    const int jt  = blockIdx.x;     // 0..23  (column tile)
    const int t   = blockIdx.y;     // 0..255
    const int dir = blockIdx.z;     // 0..1
    const float* __restrict__ W    = dir ? Wb : Wf;
    const float* __restrict__ bin  = dir ? bb : bf;   // row 0 = input bias

    __shared__ float As_t[16][68];   // [k][row] transposed A tile (padded)
    __shared__ float Bs[16][64];     // [k][col]
    __shared__ int   tok[64];

    const int tid = threadIdx.x;
    if (tid < 64) tok[tid] = x[tid * T_ + t];
    __syncthreads();

    const int tx = tid & 15;         // col group (4 cols)
    const int ty = tid >> 4;         // row group (4 rows)
    const int j0 = jt * 64;

    float acc[4][4];
#pragma unroll
    for (int r = 0; r < 4; ++r)
#pragma unroll
        for (int c = 0; c < 4; ++c) acc[r][c] = 0.f;

    for (int k0 = 0; k0 < D_; k0 += 16) {
        {
            int li = tid * 4;            // 0..1023
            int i  = li >> 4;            // row 0..63
            int kb = li & 15;            // 0,4,8,12
            float4 v = *(const float4*)&emb[(size_t)tok[i] * D_ + k0 + kb];
            As_t[kb + 0][i] = v.x;
            As_t[kb + 1][i] = v.y;
            As_t[kb + 2][i] = v.z;
            As_t[kb + 3][i] = v.w;
        }
        {
            int li = tid * 4;
            int k  = li >> 6;            // 0..15
            int j  = li & 63;
            float4 v = *(const float4*)&W[(size_t)(k0 + k) * G3 + j0 + j];
            *(float4*)&Bs[k][j] = v;
        }
        __syncthreads();
#pragma unroll
        for (int k = 0; k < 16; ++k) {
            float4 av = *(const float4*)&As_t[k][ty * 4];
            float4 bv = *(const float4*)&Bs[k][tx * 4];
            acc[0][0] += av.x * bv.x; acc[0][1] += av.x * bv.y; acc[0][2] += av.x * bv.z; acc[0][3] += av.x * bv.w;
            acc[1][0] += av.y * bv.x; acc[1][1] += av.y * bv.y; acc[1][2] += av.y * bv.z; acc[1][3] += av.y * bv.w;
            acc[2][0] += av.z * bv.x; acc[2][1] += av.z * bv.y; acc[2][2] += av.z * bv.z; acc[2][3] += av.z * bv.w;
            acc[3][0] += av.w * bv.x; acc[3][1] += av.w * bv.y; acc[3][2] += av.w * bv.z; acc[3][3] += av.w * bv.w;
        }
        __syncthreads();
    }

#pragma unroll
    for (int r = 0; r < 4; ++r) {
        int b = ty * 4 + r;
        int j = j0 + tx * 4;
        float4 o;
        o.x = acc[r][0] + bin[j + 0];
        o.y = acc[r][1] + bin[j + 1];
        o.z = acc[r][2] + bin[j + 2];
        o.w = acc[r][3] + bin[j + 3];
        *(float4*)&g_GX[dir][t][b][j] = o;
    }
}

// ======================================================================
// Kernel 2: persistent bidirectional GRU recurrence, ONE barrier per step.
// 128 blocks = dir(2) x batch-tile(2 of 32) x unit-tile(8 of 64) x k-chunk(4 of 128)
// Block permanently owns H slice [32 batches][128 units = kc slice] in smem.
// Phase A: partial h@Uw (R7 inner loop), khalf pair reduced in smem, then
//          red.global.add.f32 into triple-buffered g_P[s%3].
// dir_sync.
// Phase B: each block redundantly computes gates for ITS H slice (8x dup over
//          ut), updates h_s in place; ut==0 blocks write out/state.
// Buffer (s+1)%3 is zeroed during phase A of step s (race-free: its last
// readers were phase B of step s-2, all complete before barrier s-1).
// ======================================================================
__global__ __launch_bounds__(256, 1)
void k_recurrence(const int* __restrict__ x,
                  const float* __restrict__ Uf,
                  const float* __restrict__ Ub,
                  const float* __restrict__ bf,
                  const float* __restrict__ bb,
                  float* __restrict__ out)
{
    extern __shared__ float smem_f[];
    float* h_s    = smem_f;                        // [32][128]  (4096 f)
    float* u_s    = smem_f + 4096;                 // [128][192] (24576 f)
    ull*   red_s  = (ull*)(smem_f + 4096 + 24576); // [128][24]  (3072 ull = 6144 f)
    float* bias_s = smem_f + 4096 + 24576 + 6144;  // [3][128]   (384 f)
    int*   m_s    = (int*)(bias_s + 384);          // [32]

    const int bid = blockIdx.x;     // 0..127
    const int tid = threadIdx.x;    // 0..255
    const int kc  = bid & 3;
    const int ut  = (bid >> 2) & 7;
    const int bt  = (bid >> 5) & 1;
    const int dir = bid >> 6;
    const int b0 = bt * 32, u0 = ut * 64, k0 = kc * 128;
    const bool writer = (ut == 0);
    const float* __restrict__ Uw = dir ? Ub : Uf;

    // persistent Uw slice: u_s[k*192 + g*64 + q] = Uw[(k0+k)*G3 + g*512 + u0 + q]
    for (int v = tid; v < 128 * 48; v += 256) {          // float4 granules
        int k   = v / 48;
        int rem = v - k * 48;
        int g   = rem >> 4;
        int q   = (rem & 15) * 4;
        *(float4*)&u_s[k * 192 + g * 64 + q] =
            *(const float4*)&Uw[(size_t)(k0 + k) * G3 + g * 512 + u0 + q];
    }
    // h_s = 0
    for (int j = tid; j < 4096; j += 256) h_s[j] = 0.f;
    // recurrent bias slice for this block's kc unit range
    {
        const float* brr = (dir ? bb : bf) + G3;
        for (int j = tid; j < 384; j += 256) {
            int g = j >> 7, ul = j & 127;
            bias_s[g * 128 + ul] = brr[g * 512 + k0 + ul];
        }
    }
    // zero own slice of P[0] (per-dir partition: block (bid&63) zeros batch row (bid&63))
    {
        float2 z2 = make_float2(0.f, 0.f);
        float2* zp = (float2*)&g_P[0][dir][bid & 63][0];   // 1536 floats = 768 float2
#pragma unroll
        for (int r = 0; r < 3; ++r) __stcg(&zp[tid + r * 256], z2);
    }
    dir_sync(dir, 64);

    // ---- phase-A thread mapping (R7) ----
    const int warp  = tid >> 5;
    const int lane  = tid & 31;          // unit pair: u0 + 2*lane, +1
    const int khalf = warp >> 2;         // 0..1   (kk range)
    const int wb    = warp & 3;          // batch octet: b0 + wb*8 ..
    const int kbeg  = khalf * 64;

    float* __restrict__ state = out + (size_t)B_ * T_ * 1024;

    int cur = 0;                          // s % 3
    for (int s = 0; s < T_; ++s) {
        const int nxt = (cur == 2) ? 0 : cur + 1;
        const int t   = dir ? (T_ - 1 - s) : s;

        // ---- top-of-step: mask staging + zero next buffer slice -----------
        if (tid < 32) m_s[tid] = (x[(b0 + tid) * T_ + t] != 0);
        {
            float2 z2 = make_float2(0.f, 0.f);
            float2* zp = (float2*)&g_P[nxt][dir][bid & 63][0];
#pragma unroll
            for (int r = 0; r < 3; ++r) __stcg(&zp[tid + r * 256], z2);
        }

        // ---- phase A: partial gh = h @ Uw (f32x2, 8-batch reuse) ----------
        ull acc[3][8];
#pragma unroll
        for (int g = 0; g < 3; ++g)
#pragma unroll
            for (int i = 0; i < 8; ++i) acc[g][i] = 0ull;

        const float* hbase = &h_s[(wb * 8) * 128];
#pragma unroll 4
        for (int kk = kbeg; kk < kbeg + 64; ++kk) {
            const float* ur = &u_s[kk * 192 + 2 * lane];
            ull w0 = *(const ull*)(ur);          // gate z, units 2*lane..+1
            ull w1 = *(const ull*)(ur + 64);     // gate r
            ull w2 = *(const ull*)(ur + 128);    // gate h
#pragma unroll
            for (int i = 0; i < 8; ++i) {
                ull hv = dup2(hbase[i * 128 + kk]);
                fma2(acc[0][i], hv, w0);
                fma2(acc[1][i], hv, w1);
                fma2(acc[2][i], hv, w2);
            }
        }

        // khalf pair reduction in smem, then atomic accumulate into g_P[cur]
        ull* rb = &red_s[(wb * 32 + lane) * 24];
        if (khalf == 1) {
#pragma unroll
            for (int g = 0; g < 3; ++g)
#pragma unroll
                for (int i = 0; i < 8; ++i) rb[g * 8 + i] = acc[g][i];
        }
        __syncthreads();
        if (khalf == 0) {
#pragma unroll
            for (int g = 0; g < 3; ++g)
#pragma unroll
                for (int i = 0; i < 8; ++i) {
                    float2 a = unpk(acc[g][i]);
                    float2 c = unpk(rb[g * 8 + i]);
                    float* addr = &g_P[cur][dir][b0 + wb * 8 + i][g * 512 + u0 + 2 * lane];
                    red_add(addr,     a.x + c.x);
                    red_add(addr + 1, a.y + c.y);
                }
        }
        dir_sync(dir, 64);

        // ---- phase B: gates + update OWN H slice (dup over ut) ------------
#pragma unroll
        for (int j = 0; j < 8; ++j) {
            const int p  = j * 256 + tid;        // 0..2047 float2-pairs
            const int bl = p >> 6;               // 0..31 batch local
            const int f  = p & 63;               // 0..63 -> unit local 2f
            const int b  = b0 + bl;
            const int ug = k0 + 2 * f;           // global unit

            const float* __restrict__ Pb = &g_P[cur][dir][b][0];
            float2 pz = __ldcg((const float2*)&Pb[ug]);
            float2 pr = __ldcg((const float2*)&Pb[512 + ug]);
            float2 ph = __ldcg((const float2*)&Pb[1024 + ug]);
            const float* __restrict__ gx = &g_GX[dir][t][b][0];
            float2 xz = *(const float2*)&gx[ug];
            float2 xr = *(const float2*)&gx[512 + ug];
            float2 xh = *(const float2*)&gx[1024 + ug];
            float2 bz2 = *(const float2*)&bias_s[2 * f];
            float2 br2 = *(const float2*)&bias_s[128 + 2 * f];
            float2 bh2 = *(const float2*)&bias_s[256 + 2 * f];
            float2 hold = *(const float2*)&h_s[bl * 128 + 2 * f];
            const bool m = m_s[bl];

            float2 hn;
            {
                float z  = __fdividef(1.f, 1.f + __expf(-(xz.x + pz.x + bz2.x)));
                float rr = __fdividef(1.f, 1.f + __expf(-(xr.x + pr.x + br2.x)));
                float a  = xh.x + rr * (ph.x + bh2.x);
                float hc = 1.f - __fdividef(2.f, 1.f + __expf(2.f * a));  // tanh(a)
                hn.x = z * hold.x + (1.f - z) * hc;
                hn.x = m ? hn.x : hold.x;
            }
            {
                float z  = __fdividef(1.f, 1.f + __expf(-(xz.y + pz.y + bz2.y)));
                float rr = __fdividef(1.f, 1.f + __expf(-(xr.y + pr.y + br2.y)));
                float a  = xh.y + rr * (ph.y + bh2.y);
                float hc = 1.f - __fdividef(2.f, 1.f + __expf(2.f * a));  // tanh(a)
                hn.y = z * hold.y + (1.f - z) * hc;
                hn.y = m ? hn.y : hold.y;
            }

            *(float2*)&h_s[bl * 128 + 2 * f] = hn;
            if (writer) {
                *(float2*)&out[((size_t)b * T_ + t) * 1024 + dir * 512 + ug] = hn;
                if (s == T_ - 1)
                    *(float2*)&state[(size_t)b * 1024 + dir * 512 + ug] = hn;
            }
        }
        __syncthreads();   // h_s writes visible to next step's phase A
        cur = nxt;
    }
}

// ======================================================================
// Kernel 3: LayerNorm over last dim (1024) of out, in place
// ======================================================================
__global__ __launch_bounds__(256)
void k_layernorm(float* __restrict__ out,
                 const float* __restrict__ gamma,
                 const float* __restrict__ beta)
{
    const int row = blockIdx.x;                 // 0..16383
    float* p = out + (size_t)row * 1024;
    const int tid = threadIdx.x;

    float4 v = *(const float4*)&p[tid * 4];
    float s = v.x + v.y + v.z + v.w;
    float q = v.x * v.x + v.y * v.y + v.z * v.z + v.w * v.w;
#pragma unroll
    for (int o = 16; o; o >>= 1) {
        s += __shfl_xor_sync(0xFFFFFFFFu, s, o);
        q += __shfl_xor_sync(0xFFFFFFFFu, q, o);
    }
    __shared__ float ss[8], qq[8];
    __shared__ float mean_s, rstd_s;
    if ((tid & 31) == 0) { ss[tid >> 5] = s; qq[tid >> 5] = q; }
    __syncthreads();
    if (tid == 0) {
        float S = 0.f, Q = 0.f;
#pragma unroll
        for (int i = 0; i < 8; ++i) { S += ss[i]; Q += qq[i]; }
        float mean = S * (1.f / 1024.f);
        float var  = Q * (1.f / 1024.f) - mean * mean;
        mean_s = mean;
        rstd_s = rsqrtf(var + 1e-3f);
    }
    __syncthreads();
    float mean = mean_s, rstd = rstd_s;
    float4 g  = *(const float4*)&gamma[tid * 4];
    float4 be = *(const float4*)&beta[tid * 4];
    v.x = (v.x - mean) * rstd * g.x + be.x;
    v.y = (v.y - mean) * rstd * g.y + be.y;
    v.z = (v.z - mean) * rstd * g.z + be.z;
    v.w = (v.w - mean) * rstd * g.w + be.w;
    *(float4*)&p[tid * 4] = v;
}

// ======================================================================
extern "C" void kernel_launch(void* const* d_in, const int* in_sizes, int n_in,
                              void* d_out, int out_size)
{
    const int*   x     = (const int*)  d_in[0];
    const float* emb   = (const float*)d_in[1];
    const float* Wf    = (const float*)d_in[2];
    const float* Uf    = (const float*)d_in[3];
    const float* bf    = (const float*)d_in[4];
    const float* Wb    = (const float*)d_in[5];
    const float* Ub    = (const float*)d_in[6];
    const float* bb    = (const float*)d_in[7];
    const float* gamma = (const float*)d_in[8];
    const float* beta  = (const float*)d_in[9];
    float* out = (float*)d_out;

    // h_s 4096f + u_s 24576f + red_s 6144f + bias 384f + mask 32i
    const int smem2 = (4096 + 24576 + 6144 + 384) * 4 + 32 * 4 + 128;
    cudaFuncSetAttribute(k_recurrence, cudaFuncAttributeMaxDynamicSharedMemorySize, smem2);

    dim3 g1(G3 / 64, T_, 2);
    k_input_gemm<<<g1, 256>>>(x, emb, Wf, bf, Wb, bb);
    k_recurrence<<<128, 256, smem2>>>(x, Uf, Ub, bf, bb, out);
    k_layernorm<<<B_ * T_, 256>>>(out, gamma, beta);
}

// round 10
// speedup vs baseline: 1.2846x; 1.2846x over previous
#include <cuda_runtime.h>
#include <math.h>
#include <stdint.h>

#define B_   64
#define T_   256
#define D_   512
#define U_   512
#define G3   1536   // 3*U
#define V_   32000
#define GHC  8      // partial k-chunks for recurrence (4 kc x 2 khalf)

typedef unsigned long long ull;

// ---------------- device scratch (static: no runtime allocation) ----------
__device__ float g_GX[2][T_][B_][G3];      // e@W + b_in, per direction
__device__ float g_GHp[GHC][2][B_][G3];    // k-chunk partial sums of h@Uw
__device__ float g_H[2][B_][U_];           // hidden state
__device__ float g_embr[(size_t)V_ * D_];  // tf32-rounded embedding
__device__ float g_Wr[2][D_ * G3];         // tf32-rounded W (fwd/bwd)

// per-direction barrier state, padded to separate cache lines
struct __align__(128) BarState { unsigned int count; unsigned int gen; unsigned int pad[30]; };
__device__ BarState g_bar[2];

// ---------------- f32x2 packed helpers ------------------------------------
__device__ __forceinline__ void fma2(ull& d, ull a, ull b) {
    asm("fma.rn.f32x2 %0, %1, %2, %3;" : "=l"(d) : "l"(a), "l"(b), "l"(d));
}
__device__ __forceinline__ ull dup2(float v) {
    ull r; asm("mov.b64 %0, {%1, %1};" : "=l"(r) : "f"(v)); return r;
}
__device__ __forceinline__ float2 unpk(ull v) {
    float2 f; asm("mov.b64 {%0, %1}, %2;" : "=f"(f.x), "=f"(f.y) : "l"(v)); return f;
}
__device__ __forceinline__ float to_tf32(float v) {
    uint32_t u;
    asm("cvt.rna.tf32.f32 %0, %1;" : "=r"(u) : "f"(v));
    return __uint_as_float(u);
}

// ---------------- software barrier over one direction's 64 blocks ---------
__device__ __forceinline__ void dir_sync(int dir, unsigned nb) {
    volatile unsigned* vgen = (volatile unsigned*)&g_bar[dir].gen;
    __syncthreads();
    if (threadIdx.x == 0) {
        unsigned gen = *vgen;
        __threadfence();
        if (atomicAdd(&g_bar[dir].count, 1u) == nb - 1u) {
            g_bar[dir].count = 0u;
            __threadfence();
            atomicAdd(&g_bar[dir].gen, 1u);
        } else {
            while (*vgen == gen) { __nanosleep(64); }
        }
        __threadfence();
    }
    __syncthreads();
}

// ======================================================================
// Kernel 0: round emb / Wf / Wb to tf32 (rna) into static buffers.
// ======================================================================
__global__ __launch_bounds__(256)
void k_round(const float* __restrict__ emb,
             const float* __restrict__ Wf,
             const float* __restrict__ Wb)
{
    const size_t stride = (size_t)gridDim.x * blockDim.x;
    const size_t i0 = (size_t)blockIdx.x * blockDim.x + threadIdx.x;
    const size_t n_emb4 = (size_t)V_ * D_ / 4;
    const size_t n_w4   = (size_t)D_ * G3 / 4;

    for (size_t i = i0; i < n_emb4; i += stride) {
        float4 v = ((const float4*)emb)[i];
        v.x = to_tf32(v.x); v.y = to_tf32(v.y); v.z = to_tf32(v.z); v.w = to_tf32(v.w);
        ((float4*)g_embr)[i] = v;
    }
    for (size_t i = i0; i < n_w4; i += stride) {
        float4 a = ((const float4*)Wf)[i];
        a.x = to_tf32(a.x); a.y = to_tf32(a.y); a.z = to_tf32(a.z); a.w = to_tf32(a.w);
        ((float4*)g_Wr[0])[i] = a;
        float4 b = ((const float4*)Wb)[i];
        b.x = to_tf32(b.x); b.y = to_tf32(b.y); b.z = to_tf32(b.z); b.w = to_tf32(b.w);
        ((float4*)g_Wr[1])[i] = b;
    }
}

// ======================================================================
// Kernel 1 (mma.sync tf32): GX[dir][t][b][:] = emb[x[b][t]] @ W_dir + b_in
// Block tile 128(M: rows m=t*64+b) x 128(N), BK=32, warp tile 64x32 (2x4 grid).
// A smem [m][k] stride 36 (conflict-free frag loads); B smem [k][n] stride 132.
// ======================================================================
__global__ __launch_bounds__(256, 2)
void k_input_gemm_mma(const int* __restrict__ x,
                      const float* __restrict__ bf,
                      const float* __restrict__ bb)
{
    __shared__ float As[128 * 36];
    __shared__ float Bs[32 * 132];
    __shared__ int   tok[128];

    const int jt  = blockIdx.x;     // 0..11
    const int mt  = blockIdx.y;     // 0..127
    const int dir = blockIdx.z;
    const float* __restrict__ W   = dir ? g_Wr[1] : g_Wr[0];
    const float* __restrict__ bin = dir ? bb : bf;
    const int j0 = jt * 128;
    const int m0 = mt * 128;

    const int tid  = threadIdx.x;
    const int warp = tid >> 5;
    const int lane = tid & 31;
    const int g    = lane >> 2;      // groupID
    const int tg   = lane & 3;       // threadID_in_group
    const int wm0  = (warp >> 2) * 64;   // warp M offset (2 rows of warps)
    const int wn0  = (warp & 3) * 32;    // warp N offset (4 cols of warps)

    if (tid < 128) {
        int m = m0 + tid;
        tok[tid] = x[(m & 63) * T_ + (m >> 6)];
    }

    float acc[4][4][4];
#pragma unroll
    for (int mi = 0; mi < 4; ++mi)
#pragma unroll
        for (int ni = 0; ni < 4; ++ni)
#pragma unroll
            for (int q = 0; q < 4; ++q) acc[mi][ni][q] = 0.f;

    for (int kc = 0; kc < 16; ++kc) {
        const int k0 = kc * 32;
        __syncthreads();     // previous compute done (covers tok at kc=0)
        // stage A: 128 rows x 32 cols (embedding gather)
#pragma unroll
        for (int it = 0; it < 4; ++it) {
            int idx = it * 256 + tid;        // 0..1023 float4 units
            int r   = idx >> 3;
            int q   = (idx & 7) * 4;
            float4 v = *(const float4*)&g_embr[(size_t)tok[r] * D_ + k0 + q];
            *(float4*)&As[r * 36 + q] = v;
        }
        // stage B: 32 k-rows x 128 n-cols (natural layout)
#pragma unroll
        for (int it = 0; it < 4; ++it) {
            int idx = it * 256 + tid;
            int k   = idx >> 5;
            int n4  = (idx & 31) * 4;
            float4 v = *(const float4*)&W[(size_t)(k0 + k) * G3 + j0 + n4];
            *(float4*)&Bs[k * 132 + n4] = v;
        }
        __syncthreads();

#pragma unroll
        for (int k8 = 0; k8 < 4; ++k8) {
            const int kk = k8 * 8;
            uint32_t bfr[4][2];
#pragma unroll
            for (int ni = 0; ni < 4; ++ni) {
                int n = wn0 + ni * 8 + g;
                bfr[ni][0] = __float_as_uint(Bs[(kk + tg) * 132 + n]);
                bfr[ni][1] = __float_as_uint(Bs[(kk + tg + 4) * 132 + n]);
            }
#pragma unroll
            for (int mi = 0; mi < 4; ++mi) {
                int mr = wm0 + mi * 16 + g;
                uint32_t afr[4];
                afr[0] = __float_as_uint(As[mr * 36 + kk + tg]);
                afr[1] = __float_as_uint(As[(mr + 8) * 36 + kk + tg]);
                afr[2] = __float_as_uint(As[mr * 36 + kk + tg + 4]);
                afr[3] = __float_as_uint(As[(mr + 8) * 36 + kk + tg + 4]);
#pragma unroll
                for (int ni = 0; ni < 4; ++ni) {
                    asm volatile(
                        "mma.sync.aligned.m16n8k8.row.col.f32.tf32.tf32.f32 "
                        "{%0,%1,%2,%3}, {%4,%5,%6,%7}, {%8,%9}, {%0,%1,%2,%3};"
                        : "+f"(acc[mi][ni][0]), "+f"(acc[mi][ni][1]),
                          "+f"(acc[mi][ni][2]), "+f"(acc[mi][ni][3])
                        : "r"(afr[0]), "r"(afr[1]), "r"(afr[2]), "r"(afr[3]),
                          "r"(bfr[ni][0]), "r"(bfr[ni][1]));
                }
            }
        }
    }

    // epilogue: bias + store (c0,c1)->(row, c), (c2,c3)->(row+8, c)
#pragma unroll
    for (int mi = 0; mi < 4; ++mi) {
        int m_lo = m0 + wm0 + mi * 16 + g;
        int m_hi = m_lo + 8;
#pragma unroll
        for (int ni = 0; ni < 4; ++ni) {
            int c = j0 + wn0 + ni * 8 + 2 * tg;
            float2 bi = *(const float2*)&bin[c];
            float2 v0 = make_float2(acc[mi][ni][0] + bi.x, acc[mi][ni][1] + bi.y);
            float2 v1 = make_float2(acc[mi][ni][2] + bi.x, acc[mi][ni][3] + bi.y);
            *(float2*)&g_GX[dir][m_lo >> 6][m_lo & 63][c] = v0;
            *(float2*)&g_GX[dir][m_hi >> 6][m_hi & 63][c] = v1;
        }
    }
}

// ======================================================================
// Kernel 2: persistent bidirectional GRU recurrence (R7, proven @4330us).
// ======================================================================
__global__ __launch_bounds__(256, 1)
void k_recurrence(const int* __restrict__ x,
                  const float* __restrict__ Uf,
                  const float* __restrict__ Ub,
                  const float* __restrict__ bf,
                  const float* __restrict__ bb,
                  float* __restrict__ out)
{
    extern __shared__ float smem_f[];
    float* h_s = smem_f;                 // [32][128]
    float* u_s = smem_f + 32 * 128;      // [128][192]  (k-major, gate*64+unit)

    const int bid = blockIdx.x;     // 0..127
    const int tid = threadIdx.x;    // 0..255
    const int kc  = bid & 3;
    const int ut  = (bid >> 2) & 7;
    const int bt  = (bid >> 5) & 1;
    const int dir = bid >> 6;
    const int b0 = bt * 32, u0 = ut * 64, k0 = kc * 128;
    const float* __restrict__ Uw = dir ? Ub : Uf;

    for (int v = tid; v < 128 * 48; v += 256) {
        int k   = v / 48;
        int rem = v - k * 48;
        int g   = rem >> 4;
        int q   = (rem & 15) * 4;
        *(float4*)&u_s[k * 192 + g * 64 + q] =
            *(const float4*)&Uw[(size_t)(k0 + k) * G3 + g * 512 + u0 + q];
    }

    if (ut == 0) {
        for (int j = tid; j < 32 * 128; j += 256) {
            int b = j >> 7, k = j & 127;
            g_H[dir][b0 + b][k0 + k] = 0.f;
        }
    }
    dir_sync(dir, 64);

    const int warp  = tid >> 5;
    const int lane  = tid & 31;
    const int khalf = warp >> 2;
    const int wb    = warp & 3;
    const int kbeg  = khalf * 64;
    const int chunk = kc + 4 * khalf;

    const int bB = bid & 63;
    const float* __restrict__ brr = (dir ? bb : bf) + G3;
    const float2 bz = *(const float2*)&brr[2 * tid];
    const float2 br = *(const float2*)&brr[512 + 2 * tid];
    const float2 bh = *(const float2*)&brr[1024 + 2 * tid];

    float* __restrict__ state = out + (size_t)B_ * T_ * 1024;

    for (int s = 0; s < T_; ++s) {
        for (int j4 = tid; j4 < 1024; j4 += 256) {
            int b  = j4 >> 5;
            int kv = (j4 & 31) * 4;
            float4 v = __ldcg((const float4*)&g_H[dir][b0 + b][k0 + kv]);
            *(float4*)&h_s[b * 128 + kv] = v;
        }
        __syncthreads();

        ull acc[3][8];
#pragma unroll
        for (int g = 0; g < 3; ++g)
#pragma unroll
            for (int i = 0; i < 8; ++i) acc[g][i] = 0ull;

        const float* hbase = &h_s[(wb * 8) * 128];
#pragma unroll 4
        for (int kk = kbeg; kk < kbeg + 64; ++kk) {
            const float* ur = &u_s[kk * 192 + 2 * lane];
            ull w0 = *(const ull*)(ur);
            ull w1 = *(const ull*)(ur + 64);
            ull w2 = *(const ull*)(ur + 128);
#pragma unroll
            for (int i = 0; i < 8; ++i) {
                ull hv = dup2(hbase[i * 128 + kk]);
                fma2(acc[0][i], hv, w0);
                fma2(acc[1][i], hv, w1);
                fma2(acc[2][i], hv, w2);
            }
        }
        __syncthreads();

#pragma unroll
        for (int g = 0; g < 3; ++g)
#pragma unroll
            for (int i = 0; i < 8; ++i) {
                int b = b0 + wb * 8 + i;
                float2 w = unpk(acc[g][i]);
                __stcg((float2*)&g_GHp[chunk][dir][b][g * 512 + u0 + 2 * lane], w);
            }
        dir_sync(dir, 64);

        {
            const int t = dir ? (T_ - 1 - s) : s;
            const bool m = (x[bB * T_ + t] != 0);
            const int u = 2 * tid;

            float2 gz = bz, gr = br, gh = bh;
#pragma unroll
            for (int c = 0; c < GHC; ++c) {
                float2 a  = __ldcg((const float2*)&g_GHp[c][dir][bB][u]);
                float2 b2 = __ldcg((const float2*)&g_GHp[c][dir][bB][512 + u]);
                float2 c2 = __ldcg((const float2*)&g_GHp[c][dir][bB][1024 + u]);
                gz.x += a.x;  gz.y += a.y;
                gr.x += b2.x; gr.y += b2.y;
                gh.x += c2.x; gh.y += c2.y;
            }
            const float* __restrict__ gx = &g_GX[dir][t][bB][0];
            float2 xz = *(const float2*)&gx[u];
            float2 xr = *(const float2*)&gx[512 + u];
            float2 xh = *(const float2*)&gx[1024 + u];
            float2 hold = __ldcg((const float2*)&g_H[dir][bB][u]);

            float2 hn;
            {
                float z  = __fdividef(1.f, 1.f + __expf(-(xz.x + gz.x)));
                float rr = __fdividef(1.f, 1.f + __expf(-(xr.x + gr.x)));
                float a  = xh.x + rr * gh.x;
                float hc = 1.f - __fdividef(2.f, 1.f + __expf(2.f * a));
                hn.x = z * hold.x + (1.f - z) * hc;
                hn.x = m ? hn.x : hold.x;
            }
            {
                float z  = __fdividef(1.f, 1.f + __expf(-(xz.y + gz.y)));
                float rr = __fdividef(1.f, 1.f + __expf(-(xr.y + gr.y)));
                float a  = xh.y + rr * gh.y;
                float hc = 1.f - __fdividef(2.f, 1.f + __expf(2.f * a));
                hn.y = z * hold.y + (1.f - z) * hc;
                hn.y = m ? hn.y : hold.y;
            }

            __stcg((float2*)&g_H[dir][bB][u], hn);
            *(float2*)&out[((size_t)bB * T_ + t) * 1024 + dir * 512 + u] = hn;
            if (s == T_ - 1)
                *(float2*)&state[(size_t)bB * 1024 + dir * 512 + u] = hn;
        }
        dir_sync(dir, 64);
    }
}

// ======================================================================
// Kernel 3: LayerNorm over last dim (1024) of out, in place
// ======================================================================
__global__ __launch_bounds__(256)
void k_layernorm(float* __restrict__ out,
                 const float* __restrict__ gamma,
                 const float* __restrict__ beta)
{
    const int row = blockIdx.x;
    float* p = out + (size_t)row * 1024;
    const int tid = threadIdx.x;

    float4 v = *(const float4*)&p[tid * 4];
    float s = v.x + v.y + v.z + v.w;
    float q = v.x * v.x + v.y * v.y + v.z * v.z + v.w * v.w;
#pragma unroll
    for (int o = 16; o; o >>= 1) {
        s += __shfl_xor_sync(0xFFFFFFFFu, s, o);
        q += __shfl_xor_sync(0xFFFFFFFFu, q, o);
    }
    __shared__ float ss[8], qq[8];
    __shared__ float mean_s, rstd_s;
    if ((tid & 31) == 0) { ss[tid >> 5] = s; qq[tid >> 5] = q; }
    __syncthreads();
    if (tid == 0) {
        float S = 0.f, Q = 0.f;
#pragma unroll
        for (int i = 0; i < 8; ++i) { S += ss[i]; Q += qq[i]; }
        float mean = S * (1.f / 1024.f);
        float var  = Q * (1.f / 1024.f) - mean * mean;
        mean_s = mean;
        rstd_s = rsqrtf(var + 1e-3f);
    }
    __syncthreads();
    float mean = mean_s, rstd = rstd_s;
    float4 g  = *(const float4*)&gamma[tid * 4];
    float4 be = *(const float4*)&beta[tid * 4];
    v.x = (v.x - mean) * rstd * g.x + be.x;
    v.y = (v.y - mean) * rstd * g.y + be.y;
    v.z = (v.z - mean) * rstd * g.z + be.z;
    v.w = (v.w - mean) * rstd * g.w + be.w;
    *(float4*)&p[tid * 4] = v;
}

// ======================================================================
extern "C" void kernel_launch(void* const* d_in, const int* in_sizes, int n_in,
                              void* d_out, int out_size)
{
    const int*   x     = (const int*)  d_in[0];
    const float* emb   = (const float*)d_in[1];
    const float* Wf    = (const float*)d_in[2];
    const float* Uf    = (const float*)d_in[3];
    const float* bf    = (const float*)d_in[4];
    const float* Wb    = (const float*)d_in[5];
    const float* Ub    = (const float*)d_in[6];
    const float* bb    = (const float*)d_in[7];
    const float* gamma = (const float*)d_in[8];
    const float* beta  = (const float*)d_in[9];
    float* out = (float*)d_out;

    const int smem2 = 32 * 128 * 4 + 128 * 192 * 4;   // 16KB h_s + 96KB Uw = 112KB
    cudaFuncSetAttribute(k_recurrence, cudaFuncAttributeMaxDynamicSharedMemorySize, smem2);

    k_round<<<1024, 256>>>(emb, Wf, Wb);
    dim3 g1(G3 / 128, (T_ * B_) / 128, 2);            // 12 x 128 x 2
    k_input_gemm_mma<<<g1, 256>>>(x, bf, bb);
    k_recurrence<<<128, 256, smem2>>>(x, Uf, Ub, bf, bb, out);
    k_layernorm<<<B_ * T_, 256>>>(out, gamma, beta);
}

// round 11
// speedup vs baseline: 1.7044x; 1.3268x over previous
#include <cuda_runtime.h>
#include <cuda_bf16.h>
#include <math.h>
#include <stdint.h>

#define B_   64
#define T_   256
#define D_   512
#define U_   512
#define G3   1536   // 3*U
#define V_   32000
#define GHC  4      // partial k-chunks for recurrence (one per kc block)

typedef unsigned long long ull;

// ---------------- device scratch (static: no runtime allocation) ----------
__device__ float g_GX[2][T_][B_][G3];      // e@W + b_in, per direction
__device__ float g_GHp[GHC][2][B_][G3];    // k-chunk partial sums of h@Uw
__device__ float g_H[2][B_][U_];           // hidden state
__device__ float g_embr[(size_t)V_ * D_];  // tf32-rounded embedding
__device__ float g_Wr[2][D_ * G3];         // tf32-rounded W (fwd/bwd)

// per-direction barrier state, padded to separate cache lines
struct __align__(128) BarState { unsigned int count; unsigned int gen; unsigned int pad[30]; };
__device__ BarState g_bar[2];

// ---------------- helpers --------------------------------------------------
__device__ __forceinline__ float to_tf32(float v) {
    uint32_t u;
    asm("cvt.rna.tf32.f32 %0, %1;" : "=r"(u) : "f"(v));
    return __uint_as_float(u);
}
__device__ __forceinline__ void mma_bf16(float* c, const uint32_t* a, uint32_t b0, uint32_t b1) {
    asm volatile(
        "mma.sync.aligned.m16n8k16.row.col.f32.bf16.bf16.f32 "
        "{%0,%1,%2,%3}, {%4,%5,%6,%7}, {%8,%9}, {%0,%1,%2,%3};"
        : "+f"(c[0]), "+f"(c[1]), "+f"(c[2]), "+f"(c[3])
        : "r"(a[0]), "r"(a[1]), "r"(a[2]), "r"(a[3]), "r"(b0), "r"(b1));
}

// ---------------- software barrier over one direction's 64 blocks ---------
__device__ __forceinline__ void dir_sync(int dir, unsigned nb) {
    volatile unsigned* vgen = (volatile unsigned*)&g_bar[dir].gen;
    __syncthreads();
    if (threadIdx.x == 0) {
        unsigned gen = *vgen;
        __threadfence();
        if (atomicAdd(&g_bar[dir].count, 1u) == nb - 1u) {
            g_bar[dir].count = 0u;
            __threadfence();
            atomicAdd(&g_bar[dir].gen, 1u);
        } else {
            while (*vgen == gen) { __nanosleep(64); }
        }
        __threadfence();
    }
    __syncthreads();
}

// ======================================================================
// Kernel 0: round emb / Wf / Wb to tf32 (rna) into static buffers.
// ======================================================================
__global__ __launch_bounds__(256)
void k_round(const float* __restrict__ emb,
             const float* __restrict__ Wf,
             const float* __restrict__ Wb)
{
    const size_t stride = (size_t)gridDim.x * blockDim.x;
    const size_t i0 = (size_t)blockIdx.x * blockDim.x + threadIdx.x;
    const size_t n_emb4 = (size_t)V_ * D_ / 4;
    const size_t n_w4   = (size_t)D_ * G3 / 4;

    for (size_t i = i0; i < n_emb4; i += stride) {
        float4 v = ((const float4*)emb)[i];
        v.x = to_tf32(v.x); v.y = to_tf32(v.y); v.z = to_tf32(v.z); v.w = to_tf32(v.w);
        ((float4*)g_embr)[i] = v;
    }
    for (size_t i = i0; i < n_w4; i += stride) {
        float4 a = ((const float4*)Wf)[i];
        a.x = to_tf32(a.x); a.y = to_tf32(a.y); a.z = to_tf32(a.z); a.w = to_tf32(a.w);
        ((float4*)g_Wr[0])[i] = a;
        float4 b = ((const float4*)Wb)[i];
        b.x = to_tf32(b.x); b.y = to_tf32(b.y); b.z = to_tf32(b.z); b.w = to_tf32(b.w);
        ((float4*)g_Wr[1])[i] = b;
    }
}

// ======================================================================
// Kernel 1 (mma.sync tf32): GX[dir][t][b][:] = emb[x[b][t]] @ W_dir + b_in
// (unchanged from round 10, proven)
// ======================================================================
__global__ __launch_bounds__(256, 2)
void k_input_gemm_mma(const int* __restrict__ x,
                      const float* __restrict__ bf,
                      const float* __restrict__ bb)
{
    __shared__ float As[128 * 36];
    __shared__ float Bs[32 * 132];
    __shared__ int   tok[128];

    const int jt  = blockIdx.x;     // 0..11
    const int mt  = blockIdx.y;     // 0..127
    const int dir = blockIdx.z;
    const float* __restrict__ W   = dir ? g_Wr[1] : g_Wr[0];
    const float* __restrict__ bin = dir ? bb : bf;
    const int j0 = jt * 128;
    const int m0 = mt * 128;

    const int tid  = threadIdx.x;
    const int warp = tid >> 5;
    const int lane = tid & 31;
    const int g    = lane >> 2;
    const int tg   = lane & 3;
    const int wm0  = (warp >> 2) * 64;
    const int wn0  = (warp & 3) * 32;

    if (tid < 128) {
        int m = m0 + tid;
        tok[tid] = x[(m & 63) * T_ + (m >> 6)];
    }

    float acc[4][4][4];
#pragma unroll
    for (int mi = 0; mi < 4; ++mi)
#pragma unroll
        for (int ni = 0; ni < 4; ++ni)
#pragma unroll
            for (int q = 0; q < 4; ++q) acc[mi][ni][q] = 0.f;

    for (int kc = 0; kc < 16; ++kc) {
        const int k0 = kc * 32;
        __syncthreads();
#pragma unroll
        for (int it = 0; it < 4; ++it) {
            int idx = it * 256 + tid;
            int r   = idx >> 3;
            int q   = (idx & 7) * 4;
            float4 v = *(const float4*)&g_embr[(size_t)tok[r] * D_ + k0 + q];
            *(float4*)&As[r * 36 + q] = v;
        }
#pragma unroll
        for (int it = 0; it < 4; ++it) {
            int idx = it * 256 + tid;
            int k   = idx >> 5;
            int n4  = (idx & 31) * 4;
            float4 v = *(const float4*)&W[(size_t)(k0 + k) * G3 + j0 + n4];
            *(float4*)&Bs[k * 132 + n4] = v;
        }
        __syncthreads();

#pragma unroll
        for (int k8 = 0; k8 < 4; ++k8) {
            const int kk = k8 * 8;
            uint32_t bfr[4][2];
#pragma unroll
            for (int ni = 0; ni < 4; ++ni) {
                int n = wn0 + ni * 8 + g;
                bfr[ni][0] = __float_as_uint(Bs[(kk + tg) * 132 + n]);
                bfr[ni][1] = __float_as_uint(Bs[(kk + tg + 4) * 132 + n]);
            }
#pragma unroll
            for (int mi = 0; mi < 4; ++mi) {
                int mr = wm0 + mi * 16 + g;
                uint32_t afr[4];
                afr[0] = __float_as_uint(As[mr * 36 + kk + tg]);
                afr[1] = __float_as_uint(As[(mr + 8) * 36 + kk + tg]);
                afr[2] = __float_as_uint(As[mr * 36 + kk + tg + 4]);
                afr[3] = __float_as_uint(As[(mr + 8) * 36 + kk + tg + 4]);
#pragma unroll
                for (int ni = 0; ni < 4; ++ni) {
                    asm volatile(
                        "mma.sync.aligned.m16n8k8.row.col.f32.tf32.tf32.f32 "
                        "{%0,%1,%2,%3}, {%4,%5,%6,%7}, {%8,%9}, {%0,%1,%2,%3};"
                        : "+f"(acc[mi][ni][0]), "+f"(acc[mi][ni][1]),
                          "+f"(acc[mi][ni][2]), "+f"(acc[mi][ni][3])
                        : "r"(afr[0]), "r"(afr[1]), "r"(afr[2]), "r"(afr[3]),
                          "r"(bfr[ni][0]), "r"(bfr[ni][1]));
                }
            }
        }
    }

#pragma unroll
    for (int mi = 0; mi < 4; ++mi) {
        int m_lo = m0 + wm0 + mi * 16 + g;
        int m_hi = m_lo + 8;
#pragma unroll
        for (int ni = 0; ni < 4; ++ni) {
            int c = j0 + wn0 + ni * 8 + 2 * tg;
            float2 bi = *(const float2*)&bin[c];
            float2 v0 = make_float2(acc[mi][ni][0] + bi.x, acc[mi][ni][1] + bi.y);
            float2 v1 = make_float2(acc[mi][ni][2] + bi.x, acc[mi][ni][3] + bi.y);
            *(float2*)&g_GX[dir][m_lo >> 6][m_lo & 63][c] = v0;
            *(float2*)&g_GX[dir][m_hi >> 6][m_hi & 63][c] = v1;
        }
    }
}

// ======================================================================
// Kernel 2: persistent bidirectional GRU recurrence.
// 128 blocks = dir(2) x bt(2 of 32 batches) x ut(8 of 64 units) x kc(4 of 128 k)
// Phase A NOW on tensor cores: split-bf16 (hi+lo), 3 mma passes -> ~fp32 gh.
// U slice converted to smem bf16 hi/lo ONCE; h staged per step with hi/lo split.
// GHC = 4 (each block covers its full K=128 in-register).
// Phase B: R7 per-dir mapping, fast gate math.
// ======================================================================
__global__ __launch_bounds__(256, 1)
void k_recurrence(const int* __restrict__ x,
                  const float* __restrict__ Uf,
                  const float* __restrict__ Ub,
                  const float* __restrict__ bf,
                  const float* __restrict__ bb,
                  float* __restrict__ out)
{
    extern __shared__ __nv_bfloat16 smem_bf[];
    __nv_bfloat16* h_hi = smem_bf;                    // [32][136]
    __nv_bfloat16* h_lo = smem_bf + 32 * 136;         // [32][136]
    __nv_bfloat16* u_hi = smem_bf + 64 * 136;         // [192][136]
    __nv_bfloat16* u_lo = smem_bf + 64 * 136 + 192 * 136;

    const int bid = blockIdx.x;     // 0..127
    const int tid = threadIdx.x;    // 0..255
    const int kc  = bid & 3;
    const int ut  = (bid >> 2) & 7;
    const int bt  = (bid >> 5) & 1;
    const int dir = bid >> 6;
    const int b0 = bt * 32, u0 = ut * 64, k0 = kc * 128;
    const float* __restrict__ Uw = dir ? Ub : Uf;

    // one-time: U slice -> bf16 hi/lo, rows o = gate*64 + unit-local (192 x 128)
    for (int v = tid; v < 192 * 128; v += 256) {
        int o = v >> 7;
        int k = v & 127;
        int gate = o >> 6, ul = o & 63;
        float w = Uw[(size_t)(k0 + k) * G3 + gate * 512 + u0 + ul];
        __nv_bfloat16 wh = __float2bfloat16(w);
        u_hi[o * 136 + k] = wh;
        u_lo[o * 136 + k] = __float2bfloat16(w - __bfloat162float(wh));
    }

    // init H = 0
    if (ut == 0) {
        for (int j = tid; j < 32 * 128; j += 256) {
            int b = j >> 7, k = j & 127;
            g_H[dir][b0 + b][k0 + k] = 0.f;
        }
    }
    dir_sync(dir, 64);

    // phase-A warp tiling: warp -> m-tile (warp&1)*16, n-base (warp>>1)*48
    const int warp  = tid >> 5;
    const int lane  = tid & 31;
    const int g     = lane >> 2;
    const int tg    = lane & 3;
    const int mrow  = (warp & 1) * 16;
    const int nbase = (warp >> 1) * 48;

    // phase-B constants (per-dir mapping: block owns batch bB, all 512 units)
    const int bB = bid & 63;
    const float* __restrict__ brr = (dir ? bb : bf) + G3;
    const float2 bz  = *(const float2*)&brr[2 * tid];
    const float2 brc = *(const float2*)&brr[512 + 2 * tid];
    const float2 bhc = *(const float2*)&brr[1024 + 2 * tid];

    float* __restrict__ state = out + (size_t)B_ * T_ * 1024;

    for (int s = 0; s < T_; ++s) {
        // ---- stage h: global fp32 -> smem bf16 hi/lo ----------------------
        for (int j4 = tid; j4 < 1024; j4 += 256) {
            int b  = j4 >> 5;
            int kv = (j4 & 31) * 4;
            float4 v = __ldcg((const float4*)&g_H[dir][b0 + b][k0 + kv]);
            int base = b * 136 + kv;
            __nv_bfloat16 t0 = __float2bfloat16(v.x);
            __nv_bfloat16 t1 = __float2bfloat16(v.y);
            __nv_bfloat16 t2 = __float2bfloat16(v.z);
            __nv_bfloat16 t3 = __float2bfloat16(v.w);
            h_hi[base + 0] = t0; h_hi[base + 1] = t1;
            h_hi[base + 2] = t2; h_hi[base + 3] = t3;
            h_lo[base + 0] = __float2bfloat16(v.x - __bfloat162float(t0));
            h_lo[base + 1] = __float2bfloat16(v.y - __bfloat162float(t1));
            h_lo[base + 2] = __float2bfloat16(v.z - __bfloat162float(t2));
            h_lo[base + 3] = __float2bfloat16(v.w - __bfloat162float(t3));
        }
        __syncthreads();

        // ---- phase A: gh partial = h @ Uw via split-bf16 mma (3 passes) ---
        float acc[6][4];
#pragma unroll
        for (int ni = 0; ni < 6; ++ni)
#pragma unroll
            for (int q = 0; q < 4; ++q) acc[ni][q] = 0.f;

#pragma unroll
        for (int k8 = 0; k8 < 8; ++k8) {
            const int kk = k8 * 16 + 2 * tg;
            uint32_t ah[4], al[4];
            ah[0] = *(const uint32_t*)&h_hi[(mrow + g) * 136 + kk];
            ah[1] = *(const uint32_t*)&h_hi[(mrow + g + 8) * 136 + kk];
            ah[2] = *(const uint32_t*)&h_hi[(mrow + g) * 136 + kk + 8];
            ah[3] = *(const uint32_t*)&h_hi[(mrow + g + 8) * 136 + kk + 8];
            al[0] = *(const uint32_t*)&h_lo[(mrow + g) * 136 + kk];
            al[1] = *(const uint32_t*)&h_lo[(mrow + g + 8) * 136 + kk];
            al[2] = *(const uint32_t*)&h_lo[(mrow + g) * 136 + kk + 8];
            al[3] = *(const uint32_t*)&h_lo[(mrow + g + 8) * 136 + kk + 8];
#pragma unroll
            for (int ni = 0; ni < 6; ++ni) {
                const int orow = nbase + ni * 8 + g;
                uint32_t bh0 = *(const uint32_t*)&u_hi[orow * 136 + kk];
                uint32_t bh1 = *(const uint32_t*)&u_hi[orow * 136 + kk + 8];
                uint32_t bl0 = *(const uint32_t*)&u_lo[orow * 136 + kk];
                uint32_t bl1 = *(const uint32_t*)&u_lo[orow * 136 + kk + 8];
                mma_bf16(acc[ni], ah, bh0, bh1);
                mma_bf16(acc[ni], al, bh0, bh1);
                mma_bf16(acc[ni], ah, bl0, bl1);
            }
        }

        // store partials: c0,c1 -> row (mrow+g), c2,c3 -> row (mrow+g+8)
#pragma unroll
        for (int ni = 0; ni < 6; ++ni) {
            int o = nbase + ni * 8 + 2 * tg;
            int gate = o >> 6, ul = o & 63;
            int col = gate * 512 + u0 + ul;
            int r0 = b0 + mrow + g;
            __stcg((float2*)&g_GHp[kc][dir][r0][col],     make_float2(acc[ni][0], acc[ni][1]));
            __stcg((float2*)&g_GHp[kc][dir][r0 + 8][col], make_float2(acc[ni][2], acc[ni][3]));
        }
        dir_sync(dir, 64);

        // ---- phase B: gates + state update + output (this dir only) ------
        {
            const int t = dir ? (T_ - 1 - s) : s;
            const bool m = (x[bB * T_ + t] != 0);
            const int u = 2 * tid;

            float2 gz = bz, gr = brc, gh = bhc;
#pragma unroll
            for (int c = 0; c < GHC; ++c) {
                float2 a  = __ldcg((const float2*)&g_GHp[c][dir][bB][u]);
                float2 b2 = __ldcg((const float2*)&g_GHp[c][dir][bB][512 + u]);
                float2 c2 = __ldcg((const float2*)&g_GHp[c][dir][bB][1024 + u]);
                gz.x += a.x;  gz.y += a.y;
                gr.x += b2.x; gr.y += b2.y;
                gh.x += c2.x; gh.y += c2.y;
            }
            const float* __restrict__ gx = &g_GX[dir][t][bB][0];
            float2 xz = *(const float2*)&gx[u];
            float2 xr = *(const float2*)&gx[512 + u];
            float2 xh = *(const float2*)&gx[1024 + u];
            float2 hold = __ldcg((const float2*)&g_H[dir][bB][u]);

            float2 hn;
            {
                float z  = __fdividef(1.f, 1.f + __expf(-(xz.x + gz.x)));
                float rr = __fdividef(1.f, 1.f + __expf(-(xr.x + gr.x)));
                float a  = xh.x + rr * gh.x;
                float hc = 1.f - __fdividef(2.f, 1.f + __expf(2.f * a));
                hn.x = z * hold.x + (1.f - z) * hc;
                hn.x = m ? hn.x : hold.x;
            }
            {
                float z  = __fdividef(1.f, 1.f + __expf(-(xz.y + gz.y)));
                float rr = __fdividef(1.f, 1.f + __expf(-(xr.y + gr.y)));
                float a  = xh.y + rr * gh.y;
                float hc = 1.f - __fdividef(2.f, 1.f + __expf(2.f * a));
                hn.y = z * hold.y + (1.f - z) * hc;
                hn.y = m ? hn.y : hold.y;
            }

            __stcg((float2*)&g_H[dir][bB][u], hn);
            *(float2*)&out[((size_t)bB * T_ + t) * 1024 + dir * 512 + u] = hn;
            if (s == T_ - 1)
                *(float2*)&state[(size_t)bB * 1024 + dir * 512 + u] = hn;
        }
        dir_sync(dir, 64);
    }
}

// ======================================================================
// Kernel 3: LayerNorm over last dim (1024) of out, in place
// ======================================================================
__global__ __launch_bounds__(256)
void k_layernorm(float* __restrict__ out,
                 const float* __restrict__ gamma,
                 const float* __restrict__ beta)
{
    const int row = blockIdx.x;
    float* p = out + (size_t)row * 1024;
    const int tid = threadIdx.x;

    float4 v = *(const float4*)&p[tid * 4];
    float s = v.x + v.y + v.z + v.w;
    float q = v.x * v.x + v.y * v.y + v.z * v.z + v.w * v.w;
#pragma unroll
    for (int o = 16; o; o >>= 1) {
        s += __shfl_xor_sync(0xFFFFFFFFu, s, o);
        q += __shfl_xor_sync(0xFFFFFFFFu, q, o);
    }
    __shared__ float ss[8], qq[8];
    __shared__ float mean_s, rstd_s;
    if ((tid & 31) == 0) { ss[tid >> 5] = s; qq[tid >> 5] = q; }
    __syncthreads();
    if (tid == 0) {
        float S = 0.f, Q = 0.f;
#pragma unroll
        for (int i = 0; i < 8; ++i) { S += ss[i]; Q += qq[i]; }
        float mean = S * (1.f / 1024.f);
        float var  = Q * (1.f / 1024.f) - mean * mean;
        mean_s = mean;
        rstd_s = rsqrtf(var + 1e-3f);
    }
    __syncthreads();
    float mean = mean_s, rstd = rstd_s;
    float4 g  = *(const float4*)&gamma[tid * 4];
    float4 be = *(const float4*)&beta[tid * 4];
    v.x = (v.x - mean) * rstd * g.x + be.x;
    v.y = (v.y - mean) * rstd * g.y + be.y;
    v.z = (v.z - mean) * rstd * g.z + be.z;
    v.w = (v.w - mean) * rstd * g.w + be.w;
    *(float4*)&p[tid * 4] = v;
}

// ======================================================================
extern "C" void kernel_launch(void* const* d_in, const int* in_sizes, int n_in,
                              void* d_out, int out_size)
{
    const int*   x     = (const int*)  d_in[0];
    const float* emb   = (const float*)d_in[1];
    const float* Wf    = (const float*)d_in[2];
    const float* Uf    = (const float*)d_in[3];
    const float* bf    = (const float*)d_in[4];
    const float* Wb    = (const float*)d_in[5];
    const float* Ub    = (const float*)d_in[6];
    const float* bb    = (const float*)d_in[7];
    const float* gamma = (const float*)d_in[8];
    const float* beta  = (const float*)d_in[9];
    float* out = (float*)d_out;

    // smem: (h_hi+h_lo: 64 rows + u_hi+u_lo: 384 rows) x 136 bf16
    const int smem2 = (64 + 384) * 136 * 2;   // 121856 B
    cudaFuncSetAttribute(k_recurrence, cudaFuncAttributeMaxDynamicSharedMemorySize, smem2);

    k_round<<<1024, 256>>>(emb, Wf, Wb);
    dim3 g1(G3 / 128, (T_ * B_) / 128, 2);
    k_input_gemm_mma<<<g1, 256>>>(x, bf, bb);
    k_recurrence<<<128, 256, smem2>>>(x, Uf, Ub, bf, bb, out);
    k_layernorm<<<B_ * T_, 256>>>(out, gamma, beta);
}